// round 12
// baseline (speedup 1.0000x reference)
#include <cuda_runtime.h>
#include <cstdint>

// ComplexScaling: bilinear grid_sample, affine = s*I, align_corners=False,
// zeros padding. NHWC [32,1024,1024,2] fp32; pixel = float2.
// One block per PAIR of rows, 256 threads, SMEM-free.
//   s == 1.0f  -> exact identity: streaming copy with 256-bit (v8.f32)
//                 global loads/stores, 64 B per thread.
//   otherwise  -> global bilinear gather (verified Round-5 math).

constexpr int Hdim = 1024;
constexpr int Wdim = 1024;

__device__ __forceinline__ void ldg256_cs(float* v, const float* p) {
    asm volatile("ld.global.cs.v8.f32 {%0,%1,%2,%3,%4,%5,%6,%7}, [%8];"
                 : "=f"(v[0]), "=f"(v[1]), "=f"(v[2]), "=f"(v[3]),
                   "=f"(v[4]), "=f"(v[5]), "=f"(v[6]), "=f"(v[7])
                 : "l"(p));
}
__device__ __forceinline__ void stg256_cs(float* p, const float* v) {
    asm volatile("st.global.cs.v8.f32 [%0], {%1,%2,%3,%4,%5,%6,%7,%8};"
                 :: "l"(p),
                    "f"(v[0]), "f"(v[1]), "f"(v[2]), "f"(v[3]),
                    "f"(v[4]), "f"(v[5]), "f"(v[6]), "f"(v[7])
                 : "memory");
}

__global__ __launch_bounds__(256)
void complex_scaling_kernel(const float2* __restrict__ in,
                            const float* __restrict__ theta,
                            float2* __restrict__ out)
{
    const float s = 1.0f + __ldg(theta);
    const int t = threadIdx.x;

    if (s == 1.0f) {
        // Identity: ix == w, iy == h exactly in fp32 (<=1023.5 exact);
        // cross weights exactly 0 -> pure copy.
        // Block covers 2 rows = 4096 floats (16 KB); thread moves 16 floats
        // via two 256-bit loads + two 256-bit stores.
        const float* src = reinterpret_cast<const float*>(in) + ((int64_t)blockIdx.x << 12);
        float*       dst = reinterpret_cast<float*>(out)      + ((int64_t)blockIdx.x << 12);
        float v0[8], v1[8];
        ldg256_cs(v0, src + (t << 3));
        ldg256_cs(v1, src + (t << 3) + 2048);
        stg256_cs(dst + (t << 3),        v0);
        stg256_cs(dst + (t << 3) + 2048, v1);
        return;
    }

    // ---------------- generic path (any theta), SMEM-free ----------------
#pragma unroll
    for (int r = 0; r < 2; ++r) {
        const int row = (blockIdx.x << 1) + r;
        const int h = row & (Hdim - 1);
        const int n = row >> 10;

        // iy = ((s*yn + 1)*H - 1)/2 == s*(h - 511.5) + 511.5
        float iy  = fmaf(s, (float)h - 511.5f, 511.5f);
        float y0f = floorf(iy);
        float wy1 = iy - y0f;
        float wy0 = 1.0f - wy1;
        float y1f = y0f + 1.0f;
        wy0 = (y0f >= 0.0f && y0f <= (float)(Hdim - 1)) ? wy0 : 0.0f;
        wy1 = (y1f >= 0.0f && y1f <= (float)(Hdim - 1)) ? wy1 : 0.0f;
        int y0 = min(max((int)y0f, 0), Hdim - 1);
        int y1 = min(max((int)y1f, 0), Hdim - 1);

        const float2* img = in + ((int64_t)n << 20);   // n * H * W
        const float2* r0  = img + (y0 << 10);
        const float2* r1  = img + (y1 << 10);
        float2* orow      = out + (((int64_t)row) << 10);

        // 4 pixels per thread, interleaved: t, t+256, t+512, t+768
        int   x0[4], x1[4];
        float wx0[4], wx1[4];
#pragma unroll
        for (int k = 0; k < 4; ++k) {
            int   p   = t + (k << 8);
            float ix  = fmaf(s, (float)p - 511.5f, 511.5f);
            float x0f = floorf(ix);
            float a1  = ix - x0f;
            float a0  = 1.0f - a1;
            float x1f = x0f + 1.0f;
            wx0[k] = (x0f >= 0.0f && x0f <= (float)(Wdim - 1)) ? a0 : 0.0f;
            wx1[k] = (x1f >= 0.0f && x1f <= (float)(Wdim - 1)) ? a1 : 0.0f;
            x0[k] = min(max((int)x0f, 0), Wdim - 1);
            x1[k] = min(max((int)x1f, 0), Wdim - 1);
        }

        float2 c00[4], c01[4], c10[4], c11[4];
#pragma unroll
        for (int k = 0; k < 4; ++k) {
            c00[k] = __ldg(r0 + x0[k]);
            c01[k] = __ldg(r0 + x1[k]);
            c10[k] = __ldg(r1 + x0[k]);
            c11[k] = __ldg(r1 + x1[k]);
        }

#pragma unroll
        for (int k = 0; k < 4; ++k) {
            float wa = wy0 * wx0[k], wb = wy0 * wx1[k];
            float wc = wy1 * wx0[k], wd = wy1 * wx1[k];
            float2 v;
            v.x = wa * c00[k].x + wb * c01[k].x + wc * c10[k].x + wd * c11[k].x;
            v.y = wa * c00[k].y + wb * c01[k].y + wc * c10[k].y + wd * c11[k].y;
            orow[t + (k << 8)] = v;
        }
    }
}

extern "C" void kernel_launch(void* const* d_in, const int* in_sizes, int n_in,
                              void* d_out, int out_size)
{
    const float* inp   = (const float*)d_in[0];
    const float* theta = (const float*)d_in[1];
    float* outp        = (float*)d_out;

    const int N = 32;
    dim3 grid((N * Hdim) / 2);   // 16384 blocks, one per row pair
    dim3 block(256);

    complex_scaling_kernel<<<grid, block>>>(
        (const float2*)inp, theta, (float2*)outp);
}

// round 13
// speedup vs baseline: 1.0008x; 1.0008x over previous
#include <cuda_runtime.h>
#include <cstdint>

// ComplexScaling: bilinear grid_sample, affine = s*I, align_corners=False,
// zeros padding. NHWC [32,1024,1024,2] fp32; pixel = float2.
// FINAL: one block per output row, 256 threads, SMEM-free.
//   s == 1.0f  -> exact identity: float4 row copy (2 LDG.128 + 2 STG.128
//                 per thread). Measured at the ~6.4-6.5 TB/s HBM ceiling.
//   otherwise  -> global bilinear gather (verified math, any theta).

constexpr int Hdim = 1024;
constexpr int Wdim = 1024;

__global__ __launch_bounds__(256)
void complex_scaling_kernel(const float2* __restrict__ in,
                            const float* __restrict__ theta,
                            float2* __restrict__ out)
{
    const float s = 1.0f + __ldg(theta);

    const int row = blockIdx.x;          // n*H + h
    const int t   = threadIdx.x;

    if (s == 1.0f) {
        // Identity: ix == w, iy == h exactly in fp32 (<=1023.5 exact);
        // cross weights exactly 0 -> output row == input row.
        const float4* src = reinterpret_cast<const float4*>(in)  + ((int64_t)row << 9);
        float4*       dst = reinterpret_cast<float4*>(out)       + ((int64_t)row << 9);
        float4 v0 = __ldg(src + t);
        float4 v1 = __ldg(src + t + 256);
        dst[t]       = v0;
        dst[t + 256] = v1;
        return;
    }

    // ---------------- generic path (any theta), SMEM-free ----------------
    const int h = row & (Hdim - 1);
    const int n = row >> 10;

    // iy = ((s*yn + 1)*H - 1)/2 == s*(h - 511.5) + 511.5
    float iy  = fmaf(s, (float)h - 511.5f, 511.5f);
    float y0f = floorf(iy);
    float wy1 = iy - y0f;
    float wy0 = 1.0f - wy1;
    float y1f = y0f + 1.0f;
    wy0 = (y0f >= 0.0f && y0f <= (float)(Hdim - 1)) ? wy0 : 0.0f;
    wy1 = (y1f >= 0.0f && y1f <= (float)(Hdim - 1)) ? wy1 : 0.0f;
    int y0 = min(max((int)y0f, 0), Hdim - 1);
    int y1 = min(max((int)y1f, 0), Hdim - 1);

    const float2* img = in + ((int64_t)n << 20);   // n * H * W
    const float2* r0  = img + (y0 << 10);
    const float2* r1  = img + (y1 << 10);
    float2* orow      = out + (((int64_t)row) << 10);

    // 4 pixels per thread, interleaved: t, t+256, t+512, t+768
    int   x0[4], x1[4];
    float wx0[4], wx1[4];
#pragma unroll
    for (int k = 0; k < 4; ++k) {
        int   p   = t + (k << 8);
        float ix  = fmaf(s, (float)p - 511.5f, 511.5f);
        float x0f = floorf(ix);
        float a1  = ix - x0f;
        float a0  = 1.0f - a1;
        float x1f = x0f + 1.0f;
        wx0[k] = (x0f >= 0.0f && x0f <= (float)(Wdim - 1)) ? a0 : 0.0f;
        wx1[k] = (x1f >= 0.0f && x1f <= (float)(Wdim - 1)) ? a1 : 0.0f;
        x0[k] = min(max((int)x0f, 0), Wdim - 1);
        x1[k] = min(max((int)x1f, 0), Wdim - 1);
    }

    float2 c00[4], c01[4], c10[4], c11[4];
#pragma unroll
    for (int k = 0; k < 4; ++k) {
        c00[k] = __ldg(r0 + x0[k]);
        c01[k] = __ldg(r0 + x1[k]);
        c10[k] = __ldg(r1 + x0[k]);
        c11[k] = __ldg(r1 + x1[k]);
    }

#pragma unroll
    for (int k = 0; k < 4; ++k) {
        float wa = wy0 * wx0[k], wb = wy0 * wx1[k];
        float wc = wy1 * wx0[k], wd = wy1 * wx1[k];
        float2 r;
        r.x = wa * c00[k].x + wb * c01[k].x + wc * c10[k].x + wd * c11[k].x;
        r.y = wa * c00[k].y + wb * c01[k].y + wc * c10[k].y + wd * c11[k].y;
        orow[t + (k << 8)] = r;
    }
}

extern "C" void kernel_launch(void* const* d_in, const int* in_sizes, int n_in,
                              void* d_out, int out_size)
{
    const float* inp   = (const float*)d_in[0];
    const float* theta = (const float*)d_in[1];
    float* outp        = (float*)d_out;

    const int N = 32;
    dim3 grid(N * Hdim);   // one block per output row
    dim3 block(256);

    complex_scaling_kernel<<<grid, block>>>(
        (const float2*)inp, theta, (float2*)outp);
}

// round 14
// speedup vs baseline: 1.0020x; 1.0012x over previous
#include <cuda_runtime.h>
#include <cstdint>

// ComplexScaling: bilinear grid_sample, affine = s*I, align_corners=False,
// zeros padding. NHWC [32,1024,1024,2] fp32; pixel = float2.
// FINAL (best measured: 81.82us bench / 74.9us kernel, DRAM ~81%):
// one block per output row (n,h), 256 threads, SMEM-free.
//   s == 1.0f  -> exact identity: streaming float4 row copy.
//   otherwise  -> global-memory bilinear gather (verified math, any theta).

constexpr int Hdim = 1024;
constexpr int Wdim = 1024;

__global__ __launch_bounds__(256)
void complex_scaling_kernel(const float2* __restrict__ in,
                            const float* __restrict__ theta,
                            float2* __restrict__ out)
{
    const float s = 1.0f + __ldg(theta);

    const int row = blockIdx.x;          // n*H + h
    const int t   = threadIdx.x;

    if (s == 1.0f) {
        // Identity: ix == w, iy == h exactly in fp32 (<=1023.5 exact);
        // cross weights exactly 0 -> output row == input row.
        // 1024 float2 = 512 float4; 2 per thread, streaming (no reuse).
        const float4* src = reinterpret_cast<const float4*>(in)  + ((int64_t)row << 9);
        float4*       dst = reinterpret_cast<float4*>(out)       + ((int64_t)row << 9);
        float4 v0 = __ldcs(src + t);
        float4 v1 = __ldcs(src + t + 256);
        __stcs(dst + t,       v0);
        __stcs(dst + t + 256, v1);
        return;
    }

    // ---------------- generic path (any theta), SMEM-free ----------------
    const int h = row & (Hdim - 1);
    const int n = row >> 10;

    // y interpolation: iy = ((s*yn + 1)*H - 1)/2 == s*(h - 511.5) + 511.5
    float iy  = fmaf(s, (float)h - 511.5f, 511.5f);
    float y0f = floorf(iy);
    float wy1 = iy - y0f;
    float wy0 = 1.0f - wy1;
    float y1f = y0f + 1.0f;
    wy0 = (y0f >= 0.0f && y0f <= (float)(Hdim - 1)) ? wy0 : 0.0f;
    wy1 = (y1f >= 0.0f && y1f <= (float)(Hdim - 1)) ? wy1 : 0.0f;
    int y0 = min(max((int)y0f, 0), Hdim - 1);
    int y1 = min(max((int)y1f, 0), Hdim - 1);

    const float2* img = in + ((int64_t)n << 20);   // n * H * W
    const float2* r0  = img + (y0 << 10);
    const float2* r1  = img + (y1 << 10);
    float2* orow      = out + (((int64_t)row) << 10);

    // 4 pixels per thread, interleaved: t, t+256, t+512, t+768
    int   x0[4], x1[4];
    float wx0[4], wx1[4];
#pragma unroll
    for (int k = 0; k < 4; ++k) {
        int   p   = t + (k << 8);
        float ix  = fmaf(s, (float)p - 511.5f, 511.5f);
        float x0f = floorf(ix);
        float a1  = ix - x0f;
        float a0  = 1.0f - a1;
        float x1f = x0f + 1.0f;
        wx0[k] = (x0f >= 0.0f && x0f <= (float)(Wdim - 1)) ? a0 : 0.0f;
        wx1[k] = (x1f >= 0.0f && x1f <= (float)(Wdim - 1)) ? a1 : 0.0f;
        x0[k] = min(max((int)x0f, 0), Wdim - 1);
        x1[k] = min(max((int)x1f, 0), Wdim - 1);
    }

    float2 c00[4], c01[4], c10[4], c11[4];
#pragma unroll
    for (int k = 0; k < 4; ++k) {
        c00[k] = __ldg(r0 + x0[k]);
        c01[k] = __ldg(r0 + x1[k]);
        c10[k] = __ldg(r1 + x0[k]);
        c11[k] = __ldg(r1 + x1[k]);
    }

#pragma unroll
    for (int k = 0; k < 4; ++k) {
        float wa = wy0 * wx0[k], wb = wy0 * wx1[k];
        float wc = wy1 * wx0[k], wd = wy1 * wx1[k];
        float2 r;
        r.x = wa * c00[k].x + wb * c01[k].x + wc * c10[k].x + wd * c11[k].x;
        r.y = wa * c00[k].y + wb * c01[k].y + wc * c10[k].y + wd * c11[k].y;
        orow[t + (k << 8)] = r;
    }
}

extern "C" void kernel_launch(void* const* d_in, const int* in_sizes, int n_in,
                              void* d_out, int out_size)
{
    const float* inp   = (const float*)d_in[0];
    const float* theta = (const float*)d_in[1];
    float* outp        = (float*)d_out;

    const int N = 32;
    dim3 grid(N * Hdim);   // one block per output row
    dim3 block(256);

    complex_scaling_kernel<<<grid, block>>>(
        (const float2*)inp, theta, (float2*)outp);
}

// round 16
// speedup vs baseline: 1.0035x; 1.0016x over previous
#include <cuda_runtime.h>
#include <cstdint>

// ComplexScaling: bilinear grid_sample, affine = s*I, align_corners=False,
// zeros padding. NHWC [32,1024,1024,2] fp32; pixel = float2.
// FINAL. One block per output row (n,h), 256 threads, SMEM-free.
// Measured at the HBM/LTS ceiling: ~75us kernel, ~6.4 TB/s, traffic at the
// 512 MiB algorithmic floor. 8 structural variants all within +/-1.5%.
//   s == 1.0f  -> exact identity: streaming float4 row copy.
//   otherwise  -> global-memory bilinear gather (verified math, any theta).

constexpr int Hdim = 1024;
constexpr int Wdim = 1024;

__global__ __launch_bounds__(256)
void complex_scaling_kernel(const float2* __restrict__ in,
                            const float* __restrict__ theta,
                            float2* __restrict__ out)
{
    const float s = 1.0f + __ldg(theta);

    const int row = blockIdx.x;          // n*H + h
    const int t   = threadIdx.x;

    if (s == 1.0f) {
        // Identity: ix == w, iy == h exactly in fp32 (<=1023.5 exact);
        // cross weights exactly 0 -> output row == input row.
        // 1024 float2 = 512 float4; 2 per thread, streaming (no reuse).
        const float4* src = reinterpret_cast<const float4*>(in)  + ((int64_t)row << 9);
        float4*       dst = reinterpret_cast<float4*>(out)       + ((int64_t)row << 9);
        float4 v0 = __ldcs(src + t);
        float4 v1 = __ldcs(src + t + 256);
        __stcs(dst + t,       v0);
        __stcs(dst + t + 256, v1);
        return;
    }

    // ---------------- generic path (any theta), SMEM-free ----------------
    const int h = row & (Hdim - 1);
    const int n = row >> 10;

    // y interpolation: iy = ((s*yn + 1)*H - 1)/2 == s*(h - 511.5) + 511.5
    float iy  = fmaf(s, (float)h - 511.5f, 511.5f);
    float y0f = floorf(iy);
    float wy1 = iy - y0f;
    float wy0 = 1.0f - wy1;
    float y1f = y0f + 1.0f;
    wy0 = (y0f >= 0.0f && y0f <= (float)(Hdim - 1)) ? wy0 : 0.0f;
    wy1 = (y1f >= 0.0f && y1f <= (float)(Hdim - 1)) ? wy1 : 0.0f;
    int y0 = min(max((int)y0f, 0), Hdim - 1);
    int y1 = min(max((int)y1f, 0), Hdim - 1);

    const float2* img = in + ((int64_t)n << 20);   // n * H * W
    const float2* r0  = img + (y0 << 10);
    const float2* r1  = img + (y1 << 10);
    float2* orow      = out + (((int64_t)row) << 10);

    // 4 pixels per thread, interleaved: t, t+256, t+512, t+768
    int   x0[4], x1[4];
    float wx0[4], wx1[4];
#pragma unroll
    for (int k = 0; k < 4; ++k) {
        int   p   = t + (k << 8);
        float ix  = fmaf(s, (float)p - 511.5f, 511.5f);
        float x0f = floorf(ix);
        float a1  = ix - x0f;
        float a0  = 1.0f - a1;
        float x1f = x0f + 1.0f;
        wx0[k] = (x0f >= 0.0f && x0f <= (float)(Wdim - 1)) ? a0 : 0.0f;
        wx1[k] = (x1f >= 0.0f && x1f <= (float)(Wdim - 1)) ? a1 : 0.0f;
        x0[k] = min(max((int)x0f, 0), Wdim - 1);
        x1[k] = min(max((int)x1f, 0), Wdim - 1);
    }

    float2 c00[4], c01[4], c10[4], c11[4];
#pragma unroll
    for (int k = 0; k < 4; ++k) {
        c00[k] = __ldg(r0 + x0[k]);
        c01[k] = __ldg(r0 + x1[k]);
        c10[k] = __ldg(r1 + x0[k]);
        c11[k] = __ldg(r1 + x1[k]);
    }

#pragma unroll
    for (int k = 0; k < 4; ++k) {
        float wa = wy0 * wx0[k], wb = wy0 * wx1[k];
        float wc = wy1 * wx0[k], wd = wy1 * wx1[k];
        float2 r;
        r.x = wa * c00[k].x + wb * c01[k].x + wc * c10[k].x + wd * c11[k].x;
        r.y = wa * c00[k].y + wb * c01[k].y + wc * c10[k].y + wd * c11[k].y;
        orow[t + (k << 8)] = r;
    }
}

extern "C" void kernel_launch(void* const* d_in, const int* in_sizes, int n_in,
                              void* d_out, int out_size)
{
    const float* inp   = (const float*)d_in[0];
    const float* theta = (const float*)d_in[1];
    float* outp        = (float*)d_out;

    const int N = 32;
    dim3 grid(N * Hdim);   // one block per output row
    dim3 block(256);

    complex_scaling_kernel<<<grid, block>>>(
        (const float2*)inp, theta, (float2*)outp);
}